// round 4
// baseline (speedup 1.0000x reference)
#include <cuda_runtime.h>
#include <cuda_bf16.h>
#include <cstdint>

#define BATCH 4
#define HH 384
#define WW 384
#define NN 128
#define RAD 4
#define NSTEPS 50
#define CLIPMAX 382.999f
#define HB 8                    // half-bandwidth of M/Mw band truncation
#define BW (2 * HB + 1)         // 17 taps

// ---------------- scratch (static device allocations) ----------------
__device__ float2 g_G [BATCH * HH * WW];   // grad image of pred,  {gy,gx} *10
__device__ float2 g_GW[BATCH * HH * WW];   // grad image of |pred|,{gy,gx} *10
__device__ float  g_M [NN * NN];
__device__ float  g_Mw[NN * NN];
__device__ float2 g_pts[BATCH * NN];
__device__ float  g_wid[BATCH * NN];
__device__ float  g_part[576];
__device__ unsigned g_cnt;

// ---------------- helpers ----------------
typedef unsigned long long ull;

__device__ __forceinline__ float fsqrt_approx(float x) {
    float r; asm("sqrt.approx.f32 %0, %1;" : "=f"(r) : "f"(x)); return r;
}
__device__ __forceinline__ ull pack2(float lo, float hi) {
    ull r; asm("mov.b64 %0, {%1, %2};" : "=l"(r) : "f"(lo), "f"(hi)); return r;
}
__device__ __forceinline__ float2 unpack2(ull v) {
    float2 r; asm("mov.b64 {%0, %1}, %2;" : "=f"(r.x), "=f"(r.y) : "l"(v)); return r;
}
__device__ __forceinline__ void ffma2(ull& d, ull a, ull b) {
    asm("fma.rn.f32x2 %0, %1, %2, %0;" : "+l"(d) : "l"(a), "l"(b));
}

__device__ __forceinline__ float2 bilin(const float2* __restrict__ img, float y, float x) {
    y = fminf(fmaxf(y, 0.f), CLIPMAX);
    x = fminf(fmaxf(x, 0.f), CLIPMAX);
    float fy = floorf(y), fx = floorf(x);
    int   y0 = (int)fy,  x0 = (int)fx;
    float wy = y - fy,   wx = x - fx;
    const float2* p = img + y0 * WW + x0;
    float2 v00 = __ldg(p), v01 = __ldg(p + 1), v10 = __ldg(p + WW), v11 = __ldg(p + WW + 1);
    float w00 = (1.f - wy) * (1.f - wx);
    float w01 = (1.f - wy) * wx;
    float w10 = wy * (1.f - wx);
    float w11 = wy * wx;
    float2 r;
    r.x = v00.x * w00 + v01.x * w01 + v10.x * w10 + v11.x * w11;
    r.y = v00.y * w00 + v01.y * w01 + v10.y * w10 + v11.y * w11;
    return r;
}

__device__ __forceinline__ void prefetch_bilin(const float2* __restrict__ img, float y, float x) {
    y = fminf(fmaxf(y, 0.f), CLIPMAX);
    x = fminf(fmaxf(x, 0.f), CLIPMAX);
    int y0 = (int)floorf(y), x0 = (int)floorf(x);
    const float2* p = img + y0 * WW + x0;
    asm volatile("prefetch.global.L1 [%0];" :: "l"(p));
    asm volatile("prefetch.global.L1 [%0];" :: "l"(p + 1));
    asm volatile("prefetch.global.L1 [%0];" :: "l"(p + WW));
    asm volatile("prefetch.global.L1 [%0];" :: "l"(p + WW + 1));
}

// ---------------- kernel 1: separable 9x9 gradient conv  +  fused matgen ----------------
__global__ void __launch_bounds__(256) prep_kernel(const float* __restrict__ pred) {
    const int bid = blockIdx.x;
    const int tid = threadIdx.x;

    if (bid < 576) {
        __shared__ float2 tile[40][40];     // {p, |p|}
        __shared__ float4 hs[40][32];       // {Hg_p, Hd_p, Hg_a, Hd_a}

        const int bx = (bid % 12) * 32;
        const int by = ((bid / 12) % 12) * 32;
        const int b  = bid / 144;
        const float* img = pred + b * HH * WW;

        float g[9], dg[9], s = 0.f;
#pragma unroll
        for (int k = 0; k < 9; k++) { float t = (float)(k - 4); g[k] = expf(-t * t * 0.125f); s += g[k]; }
        float inv = 1.f / s;
#pragma unroll
        for (int k = 0; k < 9; k++) { g[k] *= inv; dg[k] = -(float)(k - 4) * 0.25f * g[k]; }

        for (int i = tid; i < 40 * 40; i += 256) {
            int ly = i / 40, lx = i % 40;
            int gy = by - RAD + ly, gx = bx - RAD + lx;
            float v = (gy >= 0 && gy < HH && gx >= 0 && gx < WW) ? img[gy * WW + gx] : 0.f;
            tile[ly][lx] = make_float2(v, fabsf(v));
        }
        __syncthreads();

        for (int i = tid; i < 40 * 32; i += 256) {
            int r = i >> 5, c = i & 31;
            float hgp = 0.f, hdp = 0.f, hga = 0.f, hda = 0.f;
#pragma unroll
            for (int kx = 0; kx < 9; kx++) {
                float2 v = tile[r][c + kx];
                hgp = fmaf(g[kx],  v.x, hgp);
                hdp = fmaf(dg[kx], v.x, hdp);
                hga = fmaf(g[kx],  v.y, hga);
                hda = fmaf(dg[kx], v.y, hda);
            }
            hs[r][c] = make_float4(hgp, hdp, hga, hda);
        }
        __syncthreads();

        const int tx = tid & 31, ty = tid >> 5;
#pragma unroll
        for (int s4 = 0; s4 < 4; s4++) {
            int oy = ty + s4 * 8;
            float c0p = 0.f, c1p = 0.f, c0a = 0.f, c1a = 0.f;
#pragma unroll
            for (int ky = 0; ky < 9; ky++) {
                float4 h = hs[oy + ky][tx];
                c0p = fmaf(dg[ky], h.x, c0p);
                c1p = fmaf(g[ky],  h.y, c1p);
                c0a = fmaf(dg[ky], h.z, c0a);
                c1a = fmaf(g[ky],  h.w, c1a);
            }
            int o = (b * HH + by + oy) * WW + bx + tx;
            g_G [o] = make_float2(10.f * c0p, 10.f * c1p);
            g_GW[o] = make_float2(10.f * c0a, 10.f * c1a);
        }
    } else {
        // ---- matgen: M, Mw via DCT eigenbasis of path Laplacian ----
        __shared__ float am[2][NN], aw[2][NN];
        const int h = tid >> 7;
        const int i = (bid - 576) * 2 + h;
        const int j = tid & 127;
        if (bid == 576 && tid == 0) g_cnt = 0;     // reset render completion counter
        {
            int k = j;
            float lam = 2.f - 2.f * cospif((float)k / 128.f);
            float c2  = (k == 0 ? 1.f : 2.f) / 128.f;
            float dm  = 1.f / (1.f + 0.001f * lam + 0.001f * lam * lam);
            float dw  = 1.f / (1.f + 0.001f * lam);
            float a   = cospif((float)(k * (2 * i + 1)) / 256.f);
            am[h][k] = c2 * dm * a;
            aw[h][k] = c2 * dw * a;
        }
        __syncthreads();
        float sm = 0.f, sw = 0.f;
#pragma unroll 4
        for (int k = 0; k < NN; k++) {
            float bq = cospif((float)(k * (2 * j + 1)) / 256.f);
            sm = fmaf(am[h][k], bq, sm);
            sw = fmaf(aw[h][k], bq, sw);
        }
        g_M [i * NN + j] = sm;
        g_Mw[i * NN + j] = sw;
    }
}

// ---------------- kernel 2: snake evolution (decoupled pts / widths) ----------------
// Widths never feed back into points, so:
//   phase 1: evolve points only (1 barrier/step via double buffer), store private
//            trajectory, prefetch G and GW lines into L1.
//   phase 2a: all 50 width-force gathers in parallel (L1-hot), private results.
//   phase 2b: width linear recursion (banded matvec only, 1 barrier/step).
__global__ void __launch_bounds__(128) snake_kernel(const float* __restrict__ nodes) {
    const int b = blockIdx.x;
    const int i = threadIdx.x;

    __shared__ __align__(16) float2 v2pad[2][NN + 2 * HB];
    __shared__ __align__(16) float  vwpad[2][NN + 2 * HB];

    // zero pads (both buffers)
    if (i < HB) {
#pragma unroll
        for (int s = 0; s < 2; s++) {
            v2pad[s][i] = make_float2(0.f, 0.f);
            v2pad[s][NN + HB + i] = make_float2(0.f, 0.f);
            vwpad[s][i] = 0.f;
            vwpad[s][NN + HB + i] = 0.f;
        }
    }

    // band rows into registers (clipped at matrix edges -> 0 coeff)
    ull   Mp[BW];
    float Mw[BW];
#pragma unroll
    for (int u = 0; u < BW; u++) {
        int j = i - HB + u;
        bool ok = (j >= 0) && (j < NN);
        float m  = ok ? __ldg(&g_M [i * NN + j]) : 0.f;
        float mw = ok ? __ldg(&g_Mw[i * NN + j]) : 0.f;
        Mp[u] = pack2(m, m);
        Mw[u] = mw;
    }

    float2 p = make_float2(__ldg(&nodes[(b * NN + i) * 2]), __ldg(&nodes[(b * NN + i) * 2 + 1]));

    const float2* Gb  = g_G  + b * HH * WW;
    const float2* GWb = g_GW + b * HH * WW;

    float2 traj[NSTEPS];          // private trajectory (regs/local)
    __syncthreads();

    // ---- phase 1: points ----
#pragma unroll 1
    for (int step = 0; step < NSTEPS; step++) {
        float2 f = bilin(Gb, p.x, p.y);
        v2pad[step & 1][HB + i] = make_float2(p.x + 0.1f * f.x, p.y + 0.1f * f.y);
        __syncthreads();
        const ull* v2u = reinterpret_cast<const ull*>(v2pad[step & 1]);
        ull a0 = 0ull, a1 = 0ull;
#pragma unroll
        for (int u = 0; u < BW - 1; u += 2) {
            ffma2(a0, Mp[u],     v2u[i + u]);
            ffma2(a1, Mp[u + 1], v2u[i + u + 1]);
        }
        ffma2(a0, Mp[BW - 1], v2u[i + BW - 1]);
        float2 ra = unpack2(a0), rb = unpack2(a1);
        p = make_float2(ra.x + rb.x, ra.y + rb.y);
        traj[step] = p;
        prefetch_bilin(GWb, p.x, p.y);   // for phase 2a
        prefetch_bilin(Gb,  p.x, p.y);   // for next step
    }
    g_pts[b * NN + i] = p;

    // ---- phase 2a: width forces (fully parallel, L1-hot) ----
    float fwv[NSTEPS];
#pragma unroll 4
    for (int t = 0; t < NSTEPS; t++) {
        float2 q  = traj[t];
        float2 fw = bilin(GWb, q.x, q.y);
        fwv[t] = 0.1f * sqrtf(fw.x * fw.x + fw.y * fw.y);
    }

    // ---- phase 2b: width recursion ----
    float wd = 1.f;
#pragma unroll 1
    for (int t = 0; t < NSTEPS; t++) {
        vwpad[t & 1][HB + i] = wd + fwv[t];
        __syncthreads();
        const float* vw = vwpad[t & 1];
        float a0 = 0.f, a1 = 0.f;
#pragma unroll
        for (int u = 0; u < BW - 1; u += 2) {
            a0 = fmaf(Mw[u],     vw[i + u],     a0);
            a1 = fmaf(Mw[u + 1], vw[i + u + 1], a1);
        }
        a0 = fmaf(Mw[BW - 1], vw[i + BW - 1], a0);
        wd = a0 + a1;
    }
    g_wid[b * NN + i] = wd;
}

// ---------------- kernel 3: render + shortlist + fused final reduce ----------------
__global__ void __launch_bounds__(256) render_kernel(const float* __restrict__ pred,
                                                     float* __restrict__ out) {
    const int b  = blockIdx.z;
    const int x0 = blockIdx.x * 32;
    const int y0 = blockIdx.y * 32;
    const int t  = threadIdx.x;

    __shared__ float4 keep[NN];
    __shared__ float  ur[NN];
    __shared__ int    wcnt[4], wofs[4], cnt;
    __shared__ float  ublim;

    float lb = 0.f; float4 nd = make_float4(0, 0, 0, 0); unsigned bmask = 0; bool pred_k = false;
    const float cy = (float)y0 + 15.5f, cx = (float)x0 + 15.5f;
    const float R = 21.95f;
    if (t < NN) {
        float2 p = g_pts[b * NN + t];
        float w  = g_wid[b * NN + t];
        nd = make_float4(p.x, p.y, w, 0.f);
        float dy = p.x - cy, dx = p.y - cx;
        float cd = sqrtf(dy * dy + dx * dx);
        lb = cd - R - w;
        ur[t] = cd + R - w;
    }
    __syncthreads();
    if (t < 64) ur[t] = fminf(ur[t], ur[t + 64]);
    __syncthreads();
    if (t < 32) {
        float v = fminf(ur[t], ur[t + 32]);
#pragma unroll
        for (int s = 16; s > 0; s >>= 1) v = fminf(v, __shfl_xor_sync(0xffffffffu, v, s));
        if (t == 0) ublim = fminf(v, 15.0f) + 0.02f;
    }
    __syncthreads();

    if (t < NN) {
        pred_k = lb < ublim;
        bmask = __ballot_sync(0xffffffffu, pred_k);
        if ((t & 31) == 0) wcnt[t >> 5] = __popc(bmask);
    }
    __syncthreads();
    if (t == 0) {
        int o = 0;
#pragma unroll
        for (int w = 0; w < 4; w++) { wofs[w] = o; o += wcnt[w]; }
        cnt = o;
    }
    __syncthreads();
    if (t < NN && pred_k) {
        int pos = wofs[t >> 5] + __popc(bmask & ((1u << (t & 31)) - 1u));
        keep[pos] = nd;
    }
    __syncthreads();

    const int n = cnt;
    const int y = y0 + (t >> 3);
    const int xg = x0 + (t & 7) * 4;
    const float fy = (float)y, fx0 = (float)xg;
    float m0 = 3.4e38f, m1 = 3.4e38f, m2 = 3.4e38f, m3 = 3.4e38f;

#pragma unroll 4
    for (int k = 0; k < n; k++) {
        float4 kk = keep[k];
        float dy  = fy - kk.x;
        float dy2 = dy * dy;
        float dx0 = fx0 - kk.y;
        float dx1 = dx0 + 1.f, dx2 = dx0 + 2.f, dx3 = dx0 + 3.f;
        m0 = fminf(m0, fsqrt_approx(fmaf(dx0, dx0, dy2)) - kk.z);
        m1 = fminf(m1, fsqrt_approx(fmaf(dx1, dx1, dy2)) - kk.z);
        m2 = fminf(m2, fsqrt_approx(fmaf(dx2, dx2, dy2)) - kk.z);
        m3 = fminf(m3, fsqrt_approx(fmaf(dx3, dx3, dy2)) - kk.z);
    }
    m0 = fminf(fmaxf(m0, 0.f), 15.f);
    m1 = fminf(fmaxf(m1, 0.f), 15.f);
    m2 = fminf(fmaxf(m2, 0.f), 15.f);
    m3 = fminf(fmaxf(m3, 0.f), 15.f);

    const float4 pv = *reinterpret_cast<const float4*>(pred + (b * HH + y) * WW + xg);
    float e0 = pv.x - m0, e1 = pv.y - m1, e2 = pv.z - m2, e3 = pv.w - m3;
    float e = e0 * e0 + e1 * e1 + e2 * e2 + e3 * e3;

    __shared__ float red[256];
    red[t] = e;
    __syncthreads();
    if (t < 128) red[t] += red[t + 128];
    __syncthreads();
    if (t < 64) red[t] += red[t + 64];
    __syncthreads();
    if (t < 32) {
        float v = red[t] + red[t + 32];
#pragma unroll
        for (int s = 16; s > 0; s >>= 1) v += __shfl_down_sync(0xffffffffu, v, s);
        if (t == 0) g_part[(b * 12 + blockIdx.y) * 12 + blockIdx.x] = v;
    }

    __shared__ bool amLast;
    if (t == 0) {
        __threadfence();
        unsigned v = atomicAdd(&g_cnt, 1u);
        amLast = (v == 575u);
    }
    __syncthreads();
    if (amLast) {
        __shared__ double sh[256];
        double s = 0.0;
        for (int idx = t; idx < 576; idx += 256) s += (double)g_part[idx];
        sh[t] = s;
        __syncthreads();
        for (int st = 128; st > 0; st >>= 1) {
            if (t < st) sh[t] += sh[t + st];
            __syncthreads();
        }
        if (t == 0) out[0] = (float)(sh[0] / (double)(BATCH * HH * WW));
    }
}

// ---------------- launcher ----------------
extern "C" void kernel_launch(void* const* d_in, const int* in_sizes, int n_in,
                              void* d_out, int out_size) {
    const float* pred  = (const float*)d_in[0];
    const float* nodes = (const float*)d_in[1];
    float* out = (float*)d_out;
    (void)in_sizes; (void)n_in; (void)out_size;

    prep_kernel<<<640, 256>>>(pred);
    snake_kernel<<<BATCH, 128>>>(nodes);
    render_kernel<<<dim3(12, 12, BATCH), 256>>>(pred, out);
}

// round 5
// speedup vs baseline: 1.4682x; 1.4682x over previous
#include <cuda_runtime.h>
#include <cuda_bf16.h>
#include <cstdint>

#define BATCH 4
#define HH 384
#define WW 384
#define NN 128
#define RAD 4
#define NSTEPS 50
#define CLIPMAX 382.999f
#define HB 8                    // half-bandwidth of M/Mw band truncation
#define BW (2 * HB + 1)         // 17 taps

// ---------------- scratch (static device allocations) ----------------
// quad planes: plane[y][x] = {gy(y,x), gx(y,x), gy(y+1,x), gx(y+1,x)}
__device__ float4 g_Gq [BATCH * HH * WW];
__device__ float4 g_GWq[BATCH * HH * WW];
__device__ float  g_M [NN * NN];
__device__ float  g_Mw[NN * NN];
__device__ float2 g_pts[BATCH * NN];
__device__ float  g_wid[BATCH * NN];
__device__ float  g_part[576];
__device__ unsigned g_cnt;

// ---------------- helpers ----------------
typedef unsigned long long ull;

__device__ __forceinline__ float fsqrt_approx(float x) {
    float r; asm("sqrt.approx.f32 %0, %1;" : "=f"(r) : "f"(x)); return r;
}
__device__ __forceinline__ ull pack2(float lo, float hi) {
    ull r; asm("mov.b64 %0, {%1, %2};" : "=l"(r) : "f"(lo), "f"(hi)); return r;
}
__device__ __forceinline__ float2 unpack2(ull v) {
    float2 r; asm("mov.b64 {%0, %1}, %2;" : "=f"(r.x), "=f"(r.y) : "l"(v)); return r;
}
__device__ __forceinline__ void ffma2(ull& d, ull a, ull b) {
    asm("fma.rn.f32x2 %0, %1, %2, %0;" : "+l"(d) : "l"(a), "l"(b));
}

// bilinear via quad layout: 2 aligned LDG.128 per tap
__device__ __forceinline__ float2 bilinq(const float4* __restrict__ plane, float y, float x) {
    y = fminf(fmaxf(y, 0.f), CLIPMAX);
    x = fminf(fmaxf(x, 0.f), CLIPMAX);
    float fy = floorf(y), fx = floorf(x);
    int   y0 = (int)fy,  x0 = (int)fx;
    float wy = y - fy,   wx = x - fx;
    const float4* p = plane + y0 * WW + x0;
    float4 qa = __ldg(p);        // {gy00, gx00, gy10, gx10}
    float4 qb = __ldg(p + 1);    // {gy01, gx01, gy11, gx11}
    float w00 = (1.f - wy) * (1.f - wx);
    float w01 = (1.f - wy) * wx;
    float w10 = wy * (1.f - wx);
    float w11 = wy * wx;
    float2 r;
    r.x = qa.x * w00 + qb.x * w01 + qa.z * w10 + qb.z * w11;
    r.y = qa.y * w00 + qb.y * w01 + qa.w * w10 + qb.w * w11;
    return r;
}

// ---------------- kernel 1: separable 9x9 gradient conv  +  fused matgen ----------------
__global__ void __launch_bounds__(256) prep_kernel(const float* __restrict__ pred) {
    const int bid = blockIdx.x;
    const int tid = threadIdx.x;

    if (bid < 576) {
        __shared__ float2 tile[40][40];     // {p, |p|}
        __shared__ float4 hs[40][32];       // {Hg_p, Hd_p, Hg_a, Hd_a}

        const int bx = (bid % 12) * 32;
        const int by = ((bid / 12) % 12) * 32;
        const int b  = bid / 144;
        const float* img = pred + b * HH * WW;

        float g[9], dg[9], s = 0.f;
#pragma unroll
        for (int k = 0; k < 9; k++) { float t = (float)(k - 4); g[k] = expf(-t * t * 0.125f); s += g[k]; }
        float inv = 1.f / s;
#pragma unroll
        for (int k = 0; k < 9; k++) { g[k] *= inv; dg[k] = -(float)(k - 4) * 0.25f * g[k]; }

        for (int i = tid; i < 40 * 40; i += 256) {
            int ly = i / 40, lx = i % 40;
            int gy = by - RAD + ly, gx = bx - RAD + lx;
            float v = (gy >= 0 && gy < HH && gx >= 0 && gx < WW) ? img[gy * WW + gx] : 0.f;
            tile[ly][lx] = make_float2(v, fabsf(v));
        }
        __syncthreads();

        for (int i = tid; i < 40 * 32; i += 256) {
            int r = i >> 5, c = i & 31;
            float hgp = 0.f, hdp = 0.f, hga = 0.f, hda = 0.f;
#pragma unroll
            for (int kx = 0; kx < 9; kx++) {
                float2 v = tile[r][c + kx];
                hgp = fmaf(g[kx],  v.x, hgp);
                hdp = fmaf(dg[kx], v.x, hdp);
                hga = fmaf(g[kx],  v.y, hga);
                hda = fmaf(dg[kx], v.y, hda);
            }
            hs[r][c] = make_float4(hgp, hdp, hga, hda);
        }
        __syncthreads();

        const int tx = tid & 31, ty = tid >> 5;
#pragma unroll
        for (int s4 = 0; s4 < 4; s4++) {
            int oy = ty + s4 * 8;
            float c0p = 0.f, c1p = 0.f, c0a = 0.f, c1a = 0.f;
#pragma unroll
            for (int ky = 0; ky < 9; ky++) {
                float4 h = hs[oy + ky][tx];
                c0p = fmaf(dg[ky], h.x, c0p);
                c1p = fmaf(g[ky],  h.y, c1p);
                c0a = fmaf(dg[ky], h.z, c0a);
                c1a = fmaf(g[ky],  h.w, c1a);
            }
            const int yg = by + oy, xg = bx + tx;
            const int o  = (b * HH + yg) * WW + xg;
            float2 Gv  = make_float2(10.f * c0p, 10.f * c1p);
            float2 GWv = make_float2(10.f * c0a, 10.f * c1a);
            // quad layout: this value is the .lo of row yg and the .hi of row yg-1
            reinterpret_cast<float2*>(&g_Gq [o])[0] = Gv;
            reinterpret_cast<float2*>(&g_GWq[o])[0] = GWv;
            if (yg > 0) {
                reinterpret_cast<float2*>(&g_Gq [o - WW])[1] = Gv;
                reinterpret_cast<float2*>(&g_GWq[o - WW])[1] = GWv;
            }
        }
    } else {
        // ---- matgen: M, Mw via DCT eigenbasis of path Laplacian ----
        __shared__ float am[2][NN], aw[2][NN];
        const int h = tid >> 7;
        const int i = (bid - 576) * 2 + h;
        const int j = tid & 127;
        if (bid == 576 && tid == 0) g_cnt = 0;     // reset render completion counter
        {
            int k = j;
            float lam = 2.f - 2.f * cospif((float)k / 128.f);
            float c2  = (k == 0 ? 1.f : 2.f) / 128.f;
            float dm  = 1.f / (1.f + 0.001f * lam + 0.001f * lam * lam);
            float dw  = 1.f / (1.f + 0.001f * lam);
            float a   = cospif((float)(k * (2 * i + 1)) / 256.f);
            am[h][k] = c2 * dm * a;
            aw[h][k] = c2 * dw * a;
        }
        __syncthreads();
        float sm = 0.f, sw = 0.f;
#pragma unroll 4
        for (int k = 0; k < NN; k++) {
            float bq = cospif((float)(k * (2 * j + 1)) / 256.f);
            sm = fmaf(am[h][k], bq, sm);
            sw = fmaf(aw[h][k], bq, sw);
        }
        g_M [i * NN + j] = sm;
        g_Mw[i * NN + j] = sw;
    }
}

// ---------------- kernel 2: snake evolution (banded matvec, quad-layout gathers) ----------------
__global__ void __launch_bounds__(128) snake_kernel(const float* __restrict__ nodes) {
    const int b = blockIdx.x;
    const int i = threadIdx.x;

    __shared__ __align__(16) float2 v2pad[NN + 2 * HB];
    __shared__ __align__(16) float  vwpad[NN + 2 * HB];
    const ull* v2u = reinterpret_cast<const ull*>(v2pad);

    if (i < HB) {
        v2pad[i] = make_float2(0.f, 0.f);
        v2pad[NN + HB + i] = make_float2(0.f, 0.f);
        vwpad[i] = 0.f;
        vwpad[NN + HB + i] = 0.f;
    }

    // band rows into registers (clipped at matrix edges -> 0 coeff)
    ull   Mp[BW];
    float Mw[BW];
#pragma unroll
    for (int u = 0; u < BW; u++) {
        int j = i - HB + u;
        bool ok = (j >= 0) && (j < NN);
        float m  = ok ? __ldg(&g_M [i * NN + j]) : 0.f;
        float mw = ok ? __ldg(&g_Mw[i * NN + j]) : 0.f;
        Mp[u] = pack2(m, m);
        Mw[u] = mw;
    }

    float2 p = make_float2(__ldg(&nodes[(b * NN + i) * 2]), __ldg(&nodes[(b * NN + i) * 2 + 1]));
    float  wd = 1.f;

    const float4* Gb  = g_Gq  + b * HH * WW;
    const float4* GWb = g_GWq + b * HH * WW;
    __syncthreads();

    for (int step = 0; step < NSTEPS; step++) {
        // A: external force at current pts
        float2 f = bilinq(Gb, p.x, p.y);
        v2pad[HB + i] = make_float2(p.x + 0.1f * f.x, p.y + 0.1f * f.y);
        __syncthreads();

        // B: pts = M @ v2 (banded), then width force at new pts
        {
            ull a0 = 0ull, a1 = 0ull;
#pragma unroll
            for (int u = 0; u < BW - 1; u += 2) {
                ffma2(a0, Mp[u],     v2u[i + u]);
                ffma2(a1, Mp[u + 1], v2u[i + u + 1]);
            }
            ffma2(a0, Mp[BW - 1], v2u[i + BW - 1]);
            float2 ra = unpack2(a0), rb = unpack2(a1);
            p = make_float2(ra.x + rb.x, ra.y + rb.y);
        }
        float2 fw = bilinq(GWb, p.x, p.y);
        vwpad[HB + i] = wd + 0.1f * sqrtf(fw.x * fw.x + fw.y * fw.y);
        __syncthreads();

        // C: wid = Mw @ vw (banded)
        {
            float a0 = 0.f, a1 = 0.f;
#pragma unroll
            for (int u = 0; u < BW - 1; u += 2) {
                a0 = fmaf(Mw[u],     vwpad[i + u],     a0);
                a1 = fmaf(Mw[u + 1], vwpad[i + u + 1], a1);
            }
            a0 = fmaf(Mw[BW - 1], vwpad[i + BW - 1], a0);
            wd = a0 + a1;
        }
    }

    g_pts[b * NN + i] = p;
    g_wid[b * NN + i] = wd;
}

// ---------------- kernel 3: render + shortlist + fused final reduce ----------------
__global__ void __launch_bounds__(256) render_kernel(const float* __restrict__ pred,
                                                     float* __restrict__ out) {
    const int b  = blockIdx.z;
    const int x0 = blockIdx.x * 32;
    const int y0 = blockIdx.y * 32;
    const int t  = threadIdx.x;

    __shared__ float4 keep[NN];
    __shared__ float  ur[NN];
    __shared__ int    wcnt[4], wofs[4], cnt;
    __shared__ float  ublim;

    float lb = 0.f; float4 nd = make_float4(0, 0, 0, 0); unsigned bmask = 0; bool pred_k = false;
    const float cy = (float)y0 + 15.5f, cx = (float)x0 + 15.5f;
    const float R = 21.95f;
    if (t < NN) {
        float2 p = g_pts[b * NN + t];
        float w  = g_wid[b * NN + t];
        nd = make_float4(p.x, p.y, w, 0.f);
        float dy = p.x - cy, dx = p.y - cx;
        float cd = sqrtf(dy * dy + dx * dx);
        lb = cd - R - w;
        ur[t] = cd + R - w;
    }
    __syncthreads();
    if (t < 64) ur[t] = fminf(ur[t], ur[t + 64]);
    __syncthreads();
    if (t < 32) {
        float v = fminf(ur[t], ur[t + 32]);
#pragma unroll
        for (int s = 16; s > 0; s >>= 1) v = fminf(v, __shfl_xor_sync(0xffffffffu, v, s));
        if (t == 0) ublim = fminf(v, 15.0f) + 0.02f;
    }
    __syncthreads();

    if (t < NN) {
        pred_k = lb < ublim;
        bmask = __ballot_sync(0xffffffffu, pred_k);
        if ((t & 31) == 0) wcnt[t >> 5] = __popc(bmask);
    }
    __syncthreads();
    if (t == 0) {
        int o = 0;
#pragma unroll
        for (int w = 0; w < 4; w++) { wofs[w] = o; o += wcnt[w]; }
        cnt = o;
    }
    __syncthreads();
    if (t < NN && pred_k) {
        int pos = wofs[t >> 5] + __popc(bmask & ((1u << (t & 31)) - 1u));
        keep[pos] = nd;
    }
    __syncthreads();

    const int n = cnt;
    const int y = y0 + (t >> 3);
    const int xg = x0 + (t & 7) * 4;
    const float fy = (float)y, fx0 = (float)xg;
    float m0 = 3.4e38f, m1 = 3.4e38f, m2 = 3.4e38f, m3 = 3.4e38f;

#pragma unroll 4
    for (int k = 0; k < n; k++) {
        float4 kk = keep[k];
        float dy  = fy - kk.x;
        float dy2 = dy * dy;
        float dx0 = fx0 - kk.y;
        float dx1 = dx0 + 1.f, dx2 = dx0 + 2.f, dx3 = dx0 + 3.f;
        m0 = fminf(m0, fsqrt_approx(fmaf(dx0, dx0, dy2)) - kk.z);
        m1 = fminf(m1, fsqrt_approx(fmaf(dx1, dx1, dy2)) - kk.z);
        m2 = fminf(m2, fsqrt_approx(fmaf(dx2, dx2, dy2)) - kk.z);
        m3 = fminf(m3, fsqrt_approx(fmaf(dx3, dx3, dy2)) - kk.z);
    }
    m0 = fminf(fmaxf(m0, 0.f), 15.f);
    m1 = fminf(fmaxf(m1, 0.f), 15.f);
    m2 = fminf(fmaxf(m2, 0.f), 15.f);
    m3 = fminf(fmaxf(m3, 0.f), 15.f);

    const float4 pv = *reinterpret_cast<const float4*>(pred + (b * HH + y) * WW + xg);
    float e0 = pv.x - m0, e1 = pv.y - m1, e2 = pv.z - m2, e3 = pv.w - m3;
    float e = e0 * e0 + e1 * e1 + e2 * e2 + e3 * e3;

    __shared__ float red[256];
    red[t] = e;
    __syncthreads();
    if (t < 128) red[t] += red[t + 128];
    __syncthreads();
    if (t < 64) red[t] += red[t + 64];
    __syncthreads();
    if (t < 32) {
        float v = red[t] + red[t + 32];
#pragma unroll
        for (int s = 16; s > 0; s >>= 1) v += __shfl_down_sync(0xffffffffu, v, s);
        if (t == 0) g_part[(b * 12 + blockIdx.y) * 12 + blockIdx.x] = v;
    }

    __shared__ bool amLast;
    if (t == 0) {
        __threadfence();
        unsigned v = atomicAdd(&g_cnt, 1u);
        amLast = (v == 575u);
    }
    __syncthreads();
    if (amLast) {
        __shared__ double sh[256];
        double s = 0.0;
        for (int idx = t; idx < 576; idx += 256) s += (double)g_part[idx];
        sh[t] = s;
        __syncthreads();
        for (int st = 128; st > 0; st >>= 1) {
            if (t < st) sh[t] += sh[t + st];
            __syncthreads();
        }
        if (t == 0) out[0] = (float)(sh[0] / (double)(BATCH * HH * WW));
    }
}

// ---------------- launcher ----------------
extern "C" void kernel_launch(void* const* d_in, const int* in_sizes, int n_in,
                              void* d_out, int out_size) {
    const float* pred  = (const float*)d_in[0];
    const float* nodes = (const float*)d_in[1];
    float* out = (float*)d_out;
    (void)in_sizes; (void)n_in; (void)out_size;

    prep_kernel<<<640, 256>>>(pred);
    snake_kernel<<<BATCH, 128>>>(nodes);
    render_kernel<<<dim3(12, 12, BATCH), 256>>>(pred, out);
}

// round 6
// speedup vs baseline: 1.7703x; 1.2058x over previous
#include <cuda_runtime.h>
#include <cuda_bf16.h>
#include <cstdint>

#define BATCH 4
#define HH 384
#define WW 384
#define NN 128
#define RAD 4
#define NSTEPS 50
#define CLIPMAX 382.999f
#define HB 8                    // half-bandwidth of M/Mw band truncation
#define BW (2 * HB + 1)         // 17 taps

// ---------------- scratch (static device allocations) ----------------
// quad planes: plane[y][x] = {gy(y,x), gx(y,x), gy(y+1,x), gx(y+1,x)}
__device__ float4 g_Gq [BATCH * HH * WW];
__device__ float4 g_GWq[BATCH * HH * WW];
__device__ float  g_M [NN * NN];
__device__ float  g_Mw[NN * NN];
__device__ float2 g_pts[BATCH * NN];
__device__ float  g_wid[BATCH * NN];
__device__ float  g_part[576];
__device__ unsigned g_cnt;

// ---------------- helpers ----------------
typedef unsigned long long ull;

__device__ __forceinline__ float fsqrt_approx(float x) {
    float r; asm("sqrt.approx.f32 %0, %1;" : "=f"(r) : "f"(x)); return r;
}
__device__ __forceinline__ ull pack2(float lo, float hi) {
    ull r; asm("mov.b64 %0, {%1, %2};" : "=l"(r) : "f"(lo), "f"(hi)); return r;
}
__device__ __forceinline__ float2 unpack2(ull v) {
    float2 r; asm("mov.b64 {%0, %1}, %2;" : "=f"(r.x), "=f"(r.y) : "l"(v)); return r;
}
__device__ __forceinline__ void ffma2(ull& d, ull a, ull b) {
    asm("fma.rn.f32x2 %0, %1, %2, %0;" : "+l"(d) : "l"(a), "l"(b));
}

// bilinear via quad layout: 2 aligned LDG.128 per tap
__device__ __forceinline__ float2 bilinq(const float4* __restrict__ plane, float y, float x) {
    y = fminf(fmaxf(y, 0.f), CLIPMAX);
    x = fminf(fmaxf(x, 0.f), CLIPMAX);
    float fy = floorf(y), fx = floorf(x);
    int   y0 = (int)fy,  x0 = (int)fx;
    float wy = y - fy,   wx = x - fx;
    const float4* p = plane + y0 * WW + x0;
    float4 qa = __ldg(p);        // {gy00, gx00, gy10, gx10}
    float4 qb = __ldg(p + 1);    // {gy01, gx01, gy11, gx11}
    float w00 = (1.f - wy) * (1.f - wx);
    float w01 = (1.f - wy) * wx;
    float w10 = wy * (1.f - wx);
    float w11 = wy * wx;
    float2 r;
    r.x = qa.x * w00 + qb.x * w01 + qa.z * w10 + qb.z * w11;
    r.y = qa.y * w00 + qb.y * w01 + qa.w * w10 + qb.w * w11;
    return r;
}

// ---------------- kernel 1: separable 9x9 gradient conv  +  fused matgen ----------------
__global__ void __launch_bounds__(256) prep_kernel(const float* __restrict__ pred) {
    const int bid = blockIdx.x;
    const int tid = threadIdx.x;

    if (bid < 576) {
        __shared__ float2 tile[40][40];     // {p, |p|}
        __shared__ float4 hs[40][32];       // {Hg_p, Hd_p, Hg_a, Hd_a}

        const int bx = (bid % 12) * 32;
        const int by = ((bid / 12) % 12) * 32;
        const int b  = bid / 144;
        const float* img = pred + b * HH * WW;

        float g[9], dg[9], s = 0.f;
#pragma unroll
        for (int k = 0; k < 9; k++) { float t = (float)(k - 4); g[k] = expf(-t * t * 0.125f); s += g[k]; }
        float inv = 1.f / s;
#pragma unroll
        for (int k = 0; k < 9; k++) { g[k] *= inv; dg[k] = -(float)(k - 4) * 0.25f * g[k]; }

        for (int i = tid; i < 40 * 40; i += 256) {
            int ly = i / 40, lx = i % 40;
            int gy = by - RAD + ly, gx = bx - RAD + lx;
            float v = (gy >= 0 && gy < HH && gx >= 0 && gx < WW) ? img[gy * WW + gx] : 0.f;
            tile[ly][lx] = make_float2(v, fabsf(v));
        }
        __syncthreads();

        for (int i = tid; i < 40 * 32; i += 256) {
            int r = i >> 5, c = i & 31;
            float hgp = 0.f, hdp = 0.f, hga = 0.f, hda = 0.f;
#pragma unroll
            for (int kx = 0; kx < 9; kx++) {
                float2 v = tile[r][c + kx];
                hgp = fmaf(g[kx],  v.x, hgp);
                hdp = fmaf(dg[kx], v.x, hdp);
                hga = fmaf(g[kx],  v.y, hga);
                hda = fmaf(dg[kx], v.y, hda);
            }
            hs[r][c] = make_float4(hgp, hdp, hga, hda);
        }
        __syncthreads();

        const int tx = tid & 31, ty = tid >> 5;
#pragma unroll
        for (int s4 = 0; s4 < 4; s4++) {
            int oy = ty + s4 * 8;
            float c0p = 0.f, c1p = 0.f, c0a = 0.f, c1a = 0.f;
#pragma unroll
            for (int ky = 0; ky < 9; ky++) {
                float4 h = hs[oy + ky][tx];
                c0p = fmaf(dg[ky], h.x, c0p);
                c1p = fmaf(g[ky],  h.y, c1p);
                c0a = fmaf(dg[ky], h.z, c0a);
                c1a = fmaf(g[ky],  h.w, c1a);
            }
            const int yg = by + oy, xg = bx + tx;
            const int o  = (b * HH + yg) * WW + xg;
            float2 Gv  = make_float2(10.f * c0p, 10.f * c1p);
            float2 GWv = make_float2(10.f * c0a, 10.f * c1a);
            // quad layout: this value is the .lo of row yg and the .hi of row yg-1
            reinterpret_cast<float2*>(&g_Gq [o])[0] = Gv;
            reinterpret_cast<float2*>(&g_GWq[o])[0] = GWv;
            if (yg > 0) {
                reinterpret_cast<float2*>(&g_Gq [o - WW])[1] = Gv;
                reinterpret_cast<float2*>(&g_GWq[o - WW])[1] = GWv;
            }
        }
    } else {
        // ---- matgen: M, Mw via DCT eigenbasis of path Laplacian ----
        __shared__ float am[2][NN], aw[2][NN];
        const int h = tid >> 7;
        const int i = (bid - 576) * 2 + h;
        const int j = tid & 127;
        if (bid == 576 && tid == 0) g_cnt = 0;     // reset render completion counter
        {
            int k = j;
            float lam = 2.f - 2.f * cospif((float)k / 128.f);
            float c2  = (k == 0 ? 1.f : 2.f) / 128.f;
            float dm  = 1.f / (1.f + 0.001f * lam + 0.001f * lam * lam);
            float dw  = 1.f / (1.f + 0.001f * lam);
            float a   = cospif((float)(k * (2 * i + 1)) / 256.f);
            am[h][k] = c2 * dm * a;
            aw[h][k] = c2 * dw * a;
        }
        __syncthreads();
        float sm = 0.f, sw = 0.f;
#pragma unroll 4
        for (int k = 0; k < NN; k++) {
            float bq = cospif((float)(k * (2 * j + 1)) / 256.f);
            sm = fmaf(am[h][k], bq, sm);
            sw = fmaf(aw[h][k], bq, sw);
        }
        g_M [i * NN + j] = sm;
        g_Mw[i * NN + j] = sw;
    }
}

// ---------------- kernel 2: snake evolution, software-pipelined ----------------
// Iteration k computes pts_k AND wid_{k-1} (width lagged one step):
//   v2 = p + 0.1*f            (f   = G(pts_{k-1}), loaded last iter)
//   vw = wd + 0.1*||fwp||     (fwp = GW(pts_{k-1}), loaded last iter; wd = wid_{k-2})
//   STS both; ONE barrier; p = M@v2; issue loads G(p), GW(p); wd = Mw@vw
// Gathers are consumed one iteration later -> latency hidden behind matvecW + wrap.
// Iteration 1's width result is discarded (wid_0 = 1); epilogue computes wid_50.
__global__ void __launch_bounds__(128) snake_kernel(const float* __restrict__ nodes) {
    const int b = blockIdx.x;
    const int i = threadIdx.x;

    __shared__ __align__(16) float2 v2pad[2][NN + 2 * HB];
    __shared__ __align__(16) float  vwpad[2][NN + 2 * HB];

    if (i < HB) {
#pragma unroll
        for (int s = 0; s < 2; s++) {
            v2pad[s][i] = make_float2(0.f, 0.f);
            v2pad[s][NN + HB + i] = make_float2(0.f, 0.f);
            vwpad[s][i] = 0.f;
            vwpad[s][NN + HB + i] = 0.f;
        }
    }

    // band rows into registers (clipped at matrix edges -> 0 coeff)
    ull   Mp[BW];
    float Mw[BW];
#pragma unroll
    for (int u = 0; u < BW; u++) {
        int j = i - HB + u;
        bool ok = (j >= 0) && (j < NN);
        float m  = ok ? __ldg(&g_M [i * NN + j]) : 0.f;
        float mw = ok ? __ldg(&g_Mw[i * NN + j]) : 0.f;
        Mp[u] = pack2(m, m);
        Mw[u] = mw;
    }

    const float4* Gb  = g_Gq  + b * HH * WW;
    const float4* GWb = g_GWq + b * HH * WW;

    float2 p = make_float2(__ldg(&nodes[(b * NN + i) * 2]), __ldg(&nodes[(b * NN + i) * 2 + 1]));
    float  wd = 1.f;

    // prologue loads at pts_0
    float2 f   = bilinq(Gb,  p.x, p.y);
    float2 fwp = bilinq(GWb, p.x, p.y);
    __syncthreads();

#pragma unroll 2
    for (int k = 1; k <= NSTEPS; k++) {
        const int buf = k & 1;
        // inputs for this iteration (f, fwp loaded at p = pts_{k-1})
        v2pad[buf][HB + i] = make_float2(p.x + 0.1f * f.x, p.y + 0.1f * f.y);
        vwpad[buf][HB + i] = wd + 0.1f * sqrtf(fwp.x * fwp.x + fwp.y * fwp.y);
        __syncthreads();

        // pts matvec
        const ull* v2u = reinterpret_cast<const ull*>(v2pad[buf]);
        ull a0 = 0ull, a1 = 0ull;
#pragma unroll
        for (int u = 0; u < BW - 1; u += 2) {
            ffma2(a0, Mp[u],     v2u[i + u]);
            ffma2(a1, Mp[u + 1], v2u[i + u + 1]);
        }
        ffma2(a0, Mp[BW - 1], v2u[i + BW - 1]);
        float2 ra = unpack2(a0), rb = unpack2(a1);
        p = make_float2(ra.x + rb.x, ra.y + rb.y);

        // issue next-iteration gathers immediately (latency overlaps width matvec)
        f   = bilinq(Gb,  p.x, p.y);
        fwp = bilinq(GWb, p.x, p.y);

        // width matvec (computes wid_{k-1}; k==1 result discarded, wid_0 = 1)
        const float* vw = vwpad[buf];
        float w0 = 0.f, w1 = 0.f;
#pragma unroll
        for (int u = 0; u < BW - 1; u += 2) {
            w0 = fmaf(Mw[u],     vw[i + u],     w0);
            w1 = fmaf(Mw[u + 1], vw[i + u + 1], w1);
        }
        w0 = fmaf(Mw[BW - 1], vw[i + BW - 1], w0);
        if (k > 1) wd = w0 + w1;
    }

    // epilogue: wid_50 = Mw @ (wid_49 + 0.1*||GW(pts_50)||)
    {
        const int buf = (NSTEPS + 1) & 1;
        vwpad[buf][HB + i] = wd + 0.1f * sqrtf(fwp.x * fwp.x + fwp.y * fwp.y);
        __syncthreads();
        const float* vw = vwpad[buf];
        float w0 = 0.f, w1 = 0.f;
#pragma unroll
        for (int u = 0; u < BW - 1; u += 2) {
            w0 = fmaf(Mw[u],     vw[i + u],     w0);
            w1 = fmaf(Mw[u + 1], vw[i + u + 1], w1);
        }
        w0 = fmaf(Mw[BW - 1], vw[i + BW - 1], w0);
        wd = w0 + w1;
    }

    g_pts[b * NN + i] = p;
    g_wid[b * NN + i] = wd;
}

// ---------------- kernel 3: render + shortlist + fused final reduce ----------------
__global__ void __launch_bounds__(256) render_kernel(const float* __restrict__ pred,
                                                     float* __restrict__ out) {
    const int b  = blockIdx.z;
    const int x0 = blockIdx.x * 32;
    const int y0 = blockIdx.y * 32;
    const int t  = threadIdx.x;

    __shared__ float4 keep[NN];
    __shared__ float  ur[NN];
    __shared__ int    wcnt[4], wofs[4], cnt;
    __shared__ float  ublim;

    float lb = 0.f; float4 nd = make_float4(0, 0, 0, 0); unsigned bmask = 0; bool pred_k = false;
    const float cy = (float)y0 + 15.5f, cx = (float)x0 + 15.5f;
    const float R = 21.95f;
    if (t < NN) {
        float2 p = g_pts[b * NN + t];
        float w  = g_wid[b * NN + t];
        nd = make_float4(p.x, p.y, w, 0.f);
        float dy = p.x - cy, dx = p.y - cx;
        float cd = sqrtf(dy * dy + dx * dx);
        lb = cd - R - w;
        ur[t] = cd + R - w;
    }
    __syncthreads();
    if (t < 64) ur[t] = fminf(ur[t], ur[t + 64]);
    __syncthreads();
    if (t < 32) {
        float v = fminf(ur[t], ur[t + 32]);
#pragma unroll
        for (int s = 16; s > 0; s >>= 1) v = fminf(v, __shfl_xor_sync(0xffffffffu, v, s));
        if (t == 0) ublim = fminf(v, 15.0f) + 0.02f;
    }
    __syncthreads();

    if (t < NN) {
        pred_k = lb < ublim;
        bmask = __ballot_sync(0xffffffffu, pred_k);
        if ((t & 31) == 0) wcnt[t >> 5] = __popc(bmask);
    }
    __syncthreads();
    if (t == 0) {
        int o = 0;
#pragma unroll
        for (int w = 0; w < 4; w++) { wofs[w] = o; o += wcnt[w]; }
        cnt = o;
    }
    __syncthreads();
    if (t < NN && pred_k) {
        int pos = wofs[t >> 5] + __popc(bmask & ((1u << (t & 31)) - 1u));
        keep[pos] = nd;
    }
    __syncthreads();

    const int n = cnt;
    const int y = y0 + (t >> 3);
    const int xg = x0 + (t & 7) * 4;
    const float fy = (float)y, fx0 = (float)xg;
    float m0 = 3.4e38f, m1 = 3.4e38f, m2 = 3.4e38f, m3 = 3.4e38f;

#pragma unroll 4
    for (int k = 0; k < n; k++) {
        float4 kk = keep[k];
        float dy  = fy - kk.x;
        float dy2 = dy * dy;
        float dx0 = fx0 - kk.y;
        float dx1 = dx0 + 1.f, dx2 = dx0 + 2.f, dx3 = dx0 + 3.f;
        m0 = fminf(m0, fsqrt_approx(fmaf(dx0, dx0, dy2)) - kk.z);
        m1 = fminf(m1, fsqrt_approx(fmaf(dx1, dx1, dy2)) - kk.z);
        m2 = fminf(m2, fsqrt_approx(fmaf(dx2, dx2, dy2)) - kk.z);
        m3 = fminf(m3, fsqrt_approx(fmaf(dx3, dx3, dy2)) - kk.z);
    }
    m0 = fminf(fmaxf(m0, 0.f), 15.f);
    m1 = fminf(fmaxf(m1, 0.f), 15.f);
    m2 = fminf(fmaxf(m2, 0.f), 15.f);
    m3 = fminf(fmaxf(m3, 0.f), 15.f);

    const float4 pv = *reinterpret_cast<const float4*>(pred + (b * HH + y) * WW + xg);
    float e0 = pv.x - m0, e1 = pv.y - m1, e2 = pv.z - m2, e3 = pv.w - m3;
    float e = e0 * e0 + e1 * e1 + e2 * e2 + e3 * e3;

    __shared__ float red[256];
    red[t] = e;
    __syncthreads();
    if (t < 128) red[t] += red[t + 128];
    __syncthreads();
    if (t < 64) red[t] += red[t + 64];
    __syncthreads();
    if (t < 32) {
        float v = red[t] + red[t + 32];
#pragma unroll
        for (int s = 16; s > 0; s >>= 1) v += __shfl_down_sync(0xffffffffu, v, s);
        if (t == 0) g_part[(b * 12 + blockIdx.y) * 12 + blockIdx.x] = v;
    }

    __shared__ bool amLast;
    if (t == 0) {
        __threadfence();
        unsigned v = atomicAdd(&g_cnt, 1u);
        amLast = (v == 575u);
    }
    __syncthreads();
    if (amLast) {
        __shared__ double sh[256];
        double s = 0.0;
        for (int idx = t; idx < 576; idx += 256) s += (double)g_part[idx];
        sh[t] = s;
        __syncthreads();
        for (int st = 128; st > 0; st >>= 1) {
            if (t < st) sh[t] += sh[t + st];
            __syncthreads();
        }
        if (t == 0) out[0] = (float)(sh[0] / (double)(BATCH * HH * WW));
    }
}

// ---------------- launcher ----------------
extern "C" void kernel_launch(void* const* d_in, const int* in_sizes, int n_in,
                              void* d_out, int out_size) {
    const float* pred  = (const float*)d_in[0];
    const float* nodes = (const float*)d_in[1];
    float* out = (float*)d_out;
    (void)in_sizes; (void)n_in; (void)out_size;

    prep_kernel<<<640, 256>>>(pred);
    snake_kernel<<<BATCH, 128>>>(nodes);
    render_kernel<<<dim3(12, 12, BATCH), 256>>>(pred, out);
}